// round 7
// baseline (speedup 1.0000x reference)
#include <cuda_runtime.h>

// Exact algebraic reduction of the reference (verified R1/R3/R5, rel_err ~7e-8):
//   relu(adder2d(x,W1)) == 0 identically  =>  out = x - 0.1 * S[o],
//   S[o] = sum |W2[o,:,:,:]|  (576 floats per o)
//
// R6: MLP_eff experiment. R1/R3/R5 all pinned at ~6us with DRAM=17% and
// regs=32 — ptxas serialized the "front-batched" loads to fit 32 regs
// (MLP_eff~2). This version forces 8 concurrently-outstanding float4 loads
// per thread (32 data regs alone), 512 blocks x 128 threads, block = one
// (b,o) slab, o = blockIdx & 63. Warp-autonomous S[o], no smem/barriers.
//
// Inputs: d_in[0]=x [8,64,64,64] f32, d_in[1]=W1 (unused), d_in[2]=W2 [64,64,3,3] f32.

static constexpr int CKK  = 64 * 3 * 3;               // 576
static constexpr int N_F4 = (8 * 64 * 64 * 64) / 4;   // 524288
static constexpr int F4_PER_BLOCK = 1024;             // one (b,o) slab
static constexpr int BLOCKS  = N_F4 / F4_PER_BLOCK;   // 512
static constexpr int THREADS = 128;

__global__ void __launch_bounds__(THREADS) fused_residual_kernel(
    const float4* __restrict__ x4,
    const float*  __restrict__ W2,
    float4* __restrict__ out4)
{
    const int t    = threadIdx.x;
    const int base = blockIdx.x * F4_PER_BLOCK;
    const int o    = blockIdx.x & 63;       // slab = b*64 + o
    const int lane = t & 31;

    // 8 independent float4 loads, all issued before any consumer.
    // 32 live data regs forces ptxas to keep them concurrently outstanding.
    float4 v0 = x4[base + t];
    float4 v1 = x4[base + t + 128];
    float4 v2 = x4[base + t + 256];
    float4 v3 = x4[base + t + 384];
    float4 v4 = x4[base + t + 512];
    float4 v5 = x4[base + t + 640];
    float4 v6 = x4[base + t + 768];
    float4 v7 = x4[base + t + 896];

    // Per-WARP S[o]: 576 floats = 128 float4 (4/lane) + 64 scalars (2/lane).
    const float*  w  = W2 + o * CKK;        // 16B-aligned (2304 % 16 == 0)
    const float4* w4 = reinterpret_cast<const float4*>(w);
    float4 a0 = w4[lane];
    float4 a1 = w4[lane + 32];
    float4 a2 = w4[lane + 64];
    float4 a3 = w4[lane + 96];
    float  b0 = w[512 + lane];
    float  b1 = w[544 + lane];

    float s = fabsf(a0.x) + fabsf(a0.y) + fabsf(a0.z) + fabsf(a0.w)
            + fabsf(a1.x) + fabsf(a1.y) + fabsf(a1.z) + fabsf(a1.w)
            + fabsf(a2.x) + fabsf(a2.y) + fabsf(a2.z) + fabsf(a2.w)
            + fabsf(a3.x) + fabsf(a3.y) + fabsf(a3.z) + fabsf(a3.w)
            + fabsf(b0) + fabsf(b1);

#pragma unroll
    for (int d = 16; d; d >>= 1)
        s += __shfl_xor_sync(0xFFFFFFFFu, s, d);

    const float bias = -0.1f * s;

    v0.x += bias; v0.y += bias; v0.z += bias; v0.w += bias;
    v1.x += bias; v1.y += bias; v1.z += bias; v1.w += bias;
    v2.x += bias; v2.y += bias; v2.z += bias; v2.w += bias;
    v3.x += bias; v3.y += bias; v3.z += bias; v3.w += bias;
    v4.x += bias; v4.y += bias; v4.z += bias; v4.w += bias;
    v5.x += bias; v5.y += bias; v5.z += bias; v5.w += bias;
    v6.x += bias; v6.y += bias; v6.z += bias; v6.w += bias;
    v7.x += bias; v7.y += bias; v7.z += bias; v7.w += bias;

    out4[base + t]       = v0;
    out4[base + t + 128] = v1;
    out4[base + t + 256] = v2;
    out4[base + t + 384] = v3;
    out4[base + t + 512] = v4;
    out4[base + t + 640] = v5;
    out4[base + t + 768] = v6;
    out4[base + t + 896] = v7;
}

extern "C" void kernel_launch(void* const* d_in, const int* in_sizes, int n_in,
                              void* d_out, int out_size) {
    const float* x  = (const float*)d_in[0];
    const float* W2 = (const float*)d_in[2];
    fused_residual_kernel<<<BLOCKS, THREADS>>>(
        reinterpret_cast<const float4*>(x), W2,
        reinterpret_cast<float4*>(d_out));
}

// round 8
// speedup vs baseline: 1.0485x; 1.0485x over previous
#include <cuda_runtime.h>
#include <cstdint>

// Exact algebraic reduction of the reference (verified R1/R3/R5/R7, rel_err ~7e-8):
//   relu(adder2d(x,W1)) == 0 identically  =>  out = x - 0.1 * S[o],
//   S[o] = sum |W2[o,:,:,:]|  (576 floats per o)
//
// R8: force MLP in SASS. R6's 8-wide front batch was re-serialized by ptxas
// (regs=32 proves it). Here the 8 x-loads are asm volatile ld.global.nc.v4.f32
// with 32 distinct live output regs — ptxas cannot reorder volatile asm or
// reuse the outputs, so all 8 loads are genuinely outstanding (MLP_p1=8).
// 512 blocks x 128 threads; block = one (b,o) slab; warp-autonomous S[o].
//
// Inputs: d_in[0]=x [8,64,64,64] f32, d_in[1]=W1 (unused), d_in[2]=W2 [64,64,3,3] f32.

static constexpr int CKK  = 64 * 3 * 3;               // 576
static constexpr int N_F4 = (8 * 64 * 64 * 64) / 4;   // 524288
static constexpr int F4_PER_BLOCK = 1024;             // one (b,o) slab
static constexpr int BLOCKS  = N_F4 / F4_PER_BLOCK;   // 512
static constexpr int THREADS = 128;

#define LDG_NC_V4(v, p)                                                   \
    asm volatile("ld.global.nc.v4.f32 {%0,%1,%2,%3}, [%4];"               \
                 : "=f"((v).x), "=f"((v).y), "=f"((v).z), "=f"((v).w)     \
                 : "l"(p))

__global__ void __launch_bounds__(THREADS, 1) fused_residual_kernel(
    const float4* __restrict__ x4,
    const float*  __restrict__ W2,
    float4* __restrict__ out4)
{
    const int t    = threadIdx.x;
    const int base = blockIdx.x * F4_PER_BLOCK;
    const int o    = blockIdx.x & 63;       // slab = b*64 + o
    const int lane = t & 31;

    const float4* p = x4 + base + t;

    // 8 forced-outstanding loads: volatile asm, distinct live output regs.
    float4 v0, v1, v2, v3, v4, v5, v6, v7;
    LDG_NC_V4(v0, p);
    LDG_NC_V4(v1, p + 128);
    LDG_NC_V4(v2, p + 256);
    LDG_NC_V4(v3, p + 384);
    LDG_NC_V4(v4, p + 512);
    LDG_NC_V4(v5, p + 640);
    LDG_NC_V4(v6, p + 768);
    LDG_NC_V4(v7, p + 896);

    // Per-WARP S[o]: 576 floats = 128 float4 (4/lane) + 64 scalars (2/lane).
    // Normal loads; L2-hot after the first wave.
    const float*  w  = W2 + o * CKK;        // 16B-aligned (2304 % 16 == 0)
    const float4* w4 = reinterpret_cast<const float4*>(w);
    float4 a0 = w4[lane];
    float4 a1 = w4[lane + 32];
    float4 a2 = w4[lane + 64];
    float4 a3 = w4[lane + 96];
    float  b0 = w[512 + lane];
    float  b1 = w[544 + lane];

    float s = fabsf(a0.x) + fabsf(a0.y) + fabsf(a0.z) + fabsf(a0.w)
            + fabsf(a1.x) + fabsf(a1.y) + fabsf(a1.z) + fabsf(a1.w)
            + fabsf(a2.x) + fabsf(a2.y) + fabsf(a2.z) + fabsf(a2.w)
            + fabsf(a3.x) + fabsf(a3.y) + fabsf(a3.z) + fabsf(a3.w)
            + fabsf(b0) + fabsf(b1);

#pragma unroll
    for (int d = 16; d; d >>= 1)
        s += __shfl_xor_sync(0xFFFFFFFFu, s, d);

    const float bias = -0.1f * s;

    v0.x += bias; v0.y += bias; v0.z += bias; v0.w += bias;
    v1.x += bias; v1.y += bias; v1.z += bias; v1.w += bias;
    v2.x += bias; v2.y += bias; v2.z += bias; v2.w += bias;
    v3.x += bias; v3.y += bias; v3.z += bias; v3.w += bias;
    v4.x += bias; v4.y += bias; v4.z += bias; v4.w += bias;
    v5.x += bias; v5.y += bias; v5.z += bias; v5.w += bias;
    v6.x += bias; v6.y += bias; v6.z += bias; v6.w += bias;
    v7.x += bias; v7.y += bias; v7.z += bias; v7.w += bias;

    float4* q = out4 + base + t;
    q[0]   = v0;
    q[128] = v1;
    q[256] = v2;
    q[384] = v3;
    q[512] = v4;
    q[640] = v5;
    q[768] = v6;
    q[896] = v7;
}

extern "C" void kernel_launch(void* const* d_in, const int* in_sizes, int n_in,
                              void* d_out, int out_size) {
    const float* x  = (const float*)d_in[0];
    const float* W2 = (const float*)d_in[2];
    fused_residual_kernel<<<BLOCKS, THREADS>>>(
        reinterpret_cast<const float4*>(x), W2,
        reinterpret_cast<float4*>(d_out));
}

// round 9
// speedup vs baseline: 1.0537x; 1.0049x over previous
#include <cuda_runtime.h>
#include <cstdint>

// Exact algebraic reduction of the reference (verified R1..R8, rel_err ~7e-8):
//   relu(adder2d(x,W1)) == 0 identically  =>  out = x - 0.1 * S[o],
//   S[o] = sum |W2[o,:,:,:]|  (576 floats per o)
//
// R9: switch the read path from LDG to cp.async.bulk (TMA/DMA path).
// R8 proved front-batched LDG (regs=55, true MLP_p1=8) does NOT move BW:
// the per-SM LDG miss-tracking path caps at ~5 B/cyc/SM. Bulk copies are
// DMA-tracked, not MSHR-tracked. Each block: one 16 KB bulk load of its
// (b,o) slab into smem, warp-autonomous S[o] hidden under the DMA wait,
// then LDS+bias+STG.128 out.
//
// Inputs: d_in[0]=x [8,64,64,64] f32, d_in[1]=W1 (unused), d_in[2]=W2 [64,64,3,3] f32.

static constexpr int CKK  = 64 * 3 * 3;               // 576
static constexpr int N_F4 = (8 * 64 * 64 * 64) / 4;   // 524288
static constexpr int F4_PER_BLOCK = 1024;             // one (b,o) slab = 16 KB
static constexpr int BLOCKS  = N_F4 / F4_PER_BLOCK;   // 512
static constexpr int THREADS = 128;
static constexpr unsigned TILE_BYTES = F4_PER_BLOCK * 16;  // 16384

__device__ __forceinline__ uint32_t smem_u32(const void* p) {
    uint32_t a;
    asm("{ .reg .u64 t; cvta.to.shared.u64 t, %1; cvt.u32.u64 %0, t; }"
        : "=r"(a) : "l"(p));
    return a;
}

__global__ void __launch_bounds__(THREADS, 1) fused_residual_kernel(
    const float4* __restrict__ x4,
    const float*  __restrict__ W2,
    float4* __restrict__ out4)
{
    __shared__ alignas(1024) float4 tile[F4_PER_BLOCK];   // 16 KB
    __shared__ alignas(8) uint64_t mbar;

    const int t    = threadIdx.x;
    const int base = blockIdx.x * F4_PER_BLOCK;
    const int o    = blockIdx.x & 63;       // slab = b*64 + o
    const int lane = t & 31;

    const uint32_t mbar_a = smem_u32(&mbar);
    const uint32_t tile_a = smem_u32(tile);

    if (t == 0) {
        asm volatile("mbarrier.init.shared.b64 [%0], 1;" :: "r"(mbar_a) : "memory");
    }
    __syncthreads();

    if (t == 0) {
        asm volatile("mbarrier.arrive.expect_tx.shared.b64 _, [%0], %1;"
                     :: "r"(mbar_a), "r"(TILE_BYTES) : "memory");
        asm volatile(
            "cp.async.bulk.shared::cluster.global.mbarrier::complete_tx::bytes "
            "[%0], [%1], %2, [%3];"
            :: "r"(tile_a), "l"(x4 + base), "r"(TILE_BYTES), "r"(mbar_a)
            : "memory");
    }

    // ---- S[o] per warp, hidden under the DMA (L2-hot after first wave) ----
    const float*  w  = W2 + o * CKK;        // 16B-aligned (2304 % 16 == 0)
    const float4* w4 = reinterpret_cast<const float4*>(w);
    float4 a0 = w4[lane];
    float4 a1 = w4[lane + 32];
    float4 a2 = w4[lane + 64];
    float4 a3 = w4[lane + 96];
    float  b0 = w[512 + lane];
    float  b1 = w[544 + lane];

    float s = fabsf(a0.x) + fabsf(a0.y) + fabsf(a0.z) + fabsf(a0.w)
            + fabsf(a1.x) + fabsf(a1.y) + fabsf(a1.z) + fabsf(a1.w)
            + fabsf(a2.x) + fabsf(a2.y) + fabsf(a2.z) + fabsf(a2.w)
            + fabsf(a3.x) + fabsf(a3.y) + fabsf(a3.z) + fabsf(a3.w)
            + fabsf(b0) + fabsf(b1);

#pragma unroll
    for (int d = 16; d; d >>= 1)
        s += __shfl_xor_sync(0xFFFFFFFFu, s, d);

    const float bias = -0.1f * s;

    // ---- wait for the bulk copy (phase 0), then stream out ----
    {
        uint32_t done;
        asm volatile(
            "{\n\t"
            ".reg .pred p;\n\t"
            "mbarrier.try_wait.parity.shared.b64 p, [%1], 0;\n\t"
            "selp.b32 %0, 1, 0, p;\n\t"
            "}" : "=r"(done) : "r"(mbar_a) : "memory");
        while (!done) {
            asm volatile(
                "{\n\t"
                ".reg .pred p;\n\t"
                "mbarrier.try_wait.parity.shared.b64 p, [%1], 0, 1000000;\n\t"
                "selp.b32 %0, 1, 0, p;\n\t"
                "}" : "=r"(done) : "r"(mbar_a) : "memory");
        }
    }

    float4* q = out4 + base + t;
#pragma unroll
    for (int i = 0; i < 8; i++) {
        float4 v = tile[t + 128 * i];
        v.x += bias; v.y += bias; v.z += bias; v.w += bias;
        q[128 * i] = v;
    }
}

extern "C" void kernel_launch(void* const* d_in, const int* in_sizes, int n_in,
                              void* d_out, int out_size) {
    const float* x  = (const float*)d_in[0];
    const float* W2 = (const float*)d_in[2];
    fused_residual_kernel<<<BLOCKS, THREADS>>>(
        reinterpret_cast<const float4*>(x), W2,
        reinterpret_cast<float4*>(d_out));
}